// round 16
// baseline (speedup 1.0000x reference)
#include <cuda_runtime.h>
#include <cuda_fp16.h>
#include <stdint.h>
#include <stddef.h>

// ---------------------------------------------------------------------------
// SuperFrame: x[t,b,:] = src_flat[b*655360 + t*240 : +640]   (overlapping view)
// y = x @ W^T + b ; out[t,b,o] = y[t,b,o] * sigmoid(y[t,b+16,o]), b in [0,16)
// out_lengths = src_lengths//3 - 2
//
// fp16 mma.sync m16n8k16 (fp32 acc), eps 2^-11 => rel_err ~3.1e-4.
// R15b: wave-scheduled (persistent regressed, reverted). BM=256, 512 threads,
// 16 warps (8m x 2n) -> 4 warps/SMSP for latency hiding; per-warp inner loop
// identical to the proven R14 kernel. 3-stage cp.async, 144KB SMEM, 1 CTA/SM.
// ---------------------------------------------------------------------------

#define N_B   32
#define N_T   8192
#define N_F   80
#define T_OUT 2728              // (8192//3*3)/3 - 2
#define K_DIM 640
#define N_DIM 1024
#define BATCH_STRIDE 655360     // N_T*N_F elements

#define BM 256
#define BN 128
#define BK 64                   // 64 halfs = 128B per row
#define STAGES 3
#define KT 10                   // K_DIM/BK
#define A_STAGE_BYTES (BM*BK*2)           // 32768
#define B_STAGE_BYTES (BN*BK*2)           // 16384
#define SMEM_BYTES (STAGES*(A_STAGE_BYTES+B_STAGE_BYTES))  // 147456

#define NMAIN 44695552LL        // 2728*16*1024

// fp16 staging buffers (device globals: allocation-free scratch)
__device__ __half g_xh[(size_t)N_B*N_T*N_F];
__device__ __half g_wh[(size_t)N_DIM*K_DIM];

// ---------------------------------------------------------------------------
// Fused prep: blocks [0,20480) cvt x, [20480,21120) cvt w, block 21120 tail.
// ---------------------------------------------------------------------------
#define XBLK 20480              // 32*8192*80 / (256*4)
#define WBLK 640                // 1024*640  / (256*4)

__global__ void prep_kernel(const float* __restrict__ src,
                            const float* __restrict__ W,
                            const void* __restrict__ lens,
                            float* __restrict__ out, long long out_sz) {
    int b = blockIdx.x;
    if (b < XBLK) {
        int i = b * 256 + threadIdx.x;               // float4 index
        float4 v = reinterpret_cast<const float4*>(src)[i];
        __half2 lo = __floats2half2_rn(v.x, v.y);
        __half2 hi = __floats2half2_rn(v.z, v.w);
        uint2 o;
        o.x = *reinterpret_cast<unsigned int*>(&lo);
        o.y = *reinterpret_cast<unsigned int*>(&hi);
        reinterpret_cast<uint2*>(g_xh)[i] = o;
    } else if (b < XBLK + WBLK) {
        int i = (b - XBLK) * 256 + threadIdx.x;
        float4 v = reinterpret_cast<const float4*>(W)[i];
        __half2 lo = __floats2half2_rn(v.x, v.y);
        __half2 hi = __floats2half2_rn(v.z, v.w);
        uint2 o;
        o.x = *reinterpret_cast<unsigned int*>(&lo);
        o.y = *reinterpret_cast<unsigned int*>(&hi);
        reinterpret_cast<uint2*>(g_wh)[i] = o;
    } else {
        int i = threadIdx.x;
        if (i >= 32) return;
        long long rem = out_sz - NMAIN;
        const int* p32 = (const int*)lens;
        long long L = (p32[1] == 0) ? ((const long long*)lens)[i]
                                    : (long long)p32[i];
        long long v = L / 3 - 2;
        if (rem == 32) {
            out[NMAIN + i] = (float)v;               // lengths as f32 values
        } else if (rem == 64) {
            ((long long*)(out + NMAIN))[i] = v;      // raw int64 layout
        }
    }
}

// ---------------------------------------------------------------------------
// PTX helpers
// ---------------------------------------------------------------------------
__device__ __forceinline__ void cpasync16(uint32_t saddr, const void* gaddr) {
    asm volatile("cp.async.cg.shared.global [%0], [%1], 16;\n"
                 :: "r"(saddr), "l"(gaddr));
}
__device__ __forceinline__ void ldm4(uint32_t* r, uint32_t addr) {
    asm volatile("ldmatrix.sync.aligned.m8n8.x4.shared.b16 {%0,%1,%2,%3}, [%4];\n"
                 : "=r"(r[0]), "=r"(r[1]), "=r"(r[2]), "=r"(r[3]) : "r"(addr));
}
__device__ __forceinline__ void mma16816(float* c, const uint32_t* a,
                                         uint32_t b0, uint32_t b1) {
    asm volatile(
        "mma.sync.aligned.m16n8k16.row.col.f32.f16.f16.f32 "
        "{%0,%1,%2,%3}, {%4,%5,%6,%7}, {%8,%9}, {%0,%1,%2,%3};\n"
        : "+f"(c[0]), "+f"(c[1]), "+f"(c[2]), "+f"(c[3])
        : "r"(a[0]), "r"(a[1]), "r"(a[2]), "r"(a[3]), "r"(b0), "r"(b1));
}

// ---------------------------------------------------------------------------
// Fused GEMM + GLU kernel.
// grid = (8 ntiles, 341 mtiles), 512 threads, 16 warps in 8(m) x 2(n).
// m = t*32 + b ; warp_m owns one full t-group of 32 batches ->
// GLU pair (b, b+16) is (m-frag 0, m-frag 1) of the SAME thread.
// Pipeline: wait_group 1 -> barrier -> issue(kt+2) -> mma(kt).
// ---------------------------------------------------------------------------
__global__ __launch_bounds__(512, 1)
void gemm_glu_kernel(const float* __restrict__ bias, float* __restrict__ out) {
    extern __shared__ char smem_raw[];
    const uint32_t sbase = (uint32_t)__cvta_generic_to_shared(smem_raw);
    const int tid  = threadIdx.x;
    const int lane = tid & 31;
    const int wid  = tid >> 5;
    const int warp_m = wid >> 1;          // 0..7
    const int warp_n = wid & 1;           // 0..1
    const int ntile = blockIdx.x;         // 0..7
    const int mtile = blockIdx.y;         // 0..340
    const int n0 = ntile * BN;

    // ---- cp.async offsets: A = 4 chunks/thread, B = 2 chunks/thread ----
    // m = mtile*256 + row, 256%32==0 -> m&31 = row&31, m>>5 = mtile*8 + row>>5
    const __half* Ab = g_xh + mtile * (8 * 240);     // + (row&31)*BS + ...
    const __half* Bb = g_wh + n0 * K_DIM;

    uint32_t gai[4], sa[4], gbi[2], sb[2];
    #pragma unroll
    for (int i = 0; i < 4; i++) {
        int c   = tid + i * 512;          // 0..2047
        int row = c >> 3;                 // 0..255
        int ch  = c & 7;                  // 16B chunk within 128B row
        gai[i] = (uint32_t)((row & 31) * BATCH_STRIDE + (row >> 5) * 240 + ch * 8);
        sa[i]  = (uint32_t)(row * 128 + ((ch ^ (row & 7)) << 4));  // xor swizzle
    }
    #pragma unroll
    for (int i = 0; i < 2; i++) {
        int c   = tid + i * 512;          // 0..1023
        int row = c >> 3;                 // 0..127
        int ch  = c & 7;
        gbi[i] = (uint32_t)(row * K_DIM + ch * 8);
        sb[i]  = (uint32_t)(row * 128 + ((ch ^ (row & 7)) << 4));
    }

    auto issue = [&](int st, int ko) {    // ko in half elements
        uint32_t aoff = sbase + st * A_STAGE_BYTES;
        uint32_t boff = sbase + STAGES * A_STAGE_BYTES + st * B_STAGE_BYTES;
        #pragma unroll
        for (int i = 0; i < 4; i++) cpasync16(aoff + sa[i], Ab + gai[i] + ko);
        #pragma unroll
        for (int i = 0; i < 2; i++) cpasync16(boff + sb[i], Bb + gbi[i] + ko);
    };

    float acc[2][8][4] = {};

    // prologue: fill first 2 stages
    issue(0, 0);
    asm volatile("cp.async.commit_group;\n");
    issue(1, BK);
    asm volatile("cp.async.commit_group;\n");

    #pragma unroll 1
    for (int kt = 0; kt < KT; kt++) {
        asm volatile("cp.async.wait_group 1;\n");   // stage kt landed
        __syncthreads();
        if (kt + 2 < KT) issue((kt + 2) % STAGES, (kt + 2) * BK);
        asm volatile("cp.async.commit_group;\n");   // unconditional: keeps count

        uint32_t sA = sbase + (kt % STAGES) * A_STAGE_BYTES;
        uint32_t sB = sbase + STAGES * A_STAGE_BYTES + (kt % STAGES) * B_STAGE_BYTES;

        #pragma unroll
        for (int s = 0; s < 4; s++) {     // 4 k16-steps per BK=64
            uint32_t a[2][4];
            #pragma unroll
            for (int mi = 0; mi < 2; mi++) {
                int rl = warp_m * 32 + mi * 16 + (lane & 15);   // 0..255
                int ch = s * 2 + (lane >> 4);
                ldm4(a[mi], sA + rl * 128 + ((ch ^ (rl & 7)) << 4));
            }
            uint32_t bfr[4][4];
            #pragma unroll
            for (int g = 0; g < 4; g++) { // each x4 covers two n8 frags
                int nl = warp_n * 64 + g * 16 + ((lane >> 4) << 3) + (lane & 7);
                int ch = s * 2 + ((lane >> 3) & 1);
                ldm4(bfr[g], sB + nl * 128 + ((ch ^ (nl & 7)) << 4));
            }
            #pragma unroll
            for (int mi = 0; mi < 2; mi++)
                #pragma unroll
                for (int nj = 0; nj < 8; nj++)
                    mma16816(acc[mi][nj], a[mi],
                             bfr[nj >> 1][(nj & 1) * 2],
                             bfr[nj >> 1][(nj & 1) * 2 + 1]);
        }
    }

    // ---- fused GLU epilogue (thread-local (b, b+16) pairing) ----
    const int brow  = lane >> 2;          // 0..7
    const int col2  = (lane & 3) * 2;
    const int t_out = mtile * 8 + warp_m; // 0..2727
    #pragma unroll
    for (int nj = 0; nj < 8; nj++) {
        int o = n0 + warp_n * 64 + nj * 8 + col2;
        float bx = bias[o], by = bias[o + 1];
        float l0 = acc[0][nj][0] + bx, l1 = acc[0][nj][1] + by;
        float q0 = acc[1][nj][0] + bx, q1 = acc[1][nj][1] + by;
        float2 r0 = make_float2(l0 * (1.0f / (1.0f + __expf(-q0))),
                                l1 * (1.0f / (1.0f + __expf(-q1))));
        *reinterpret_cast<float2*>(
            out + ((size_t)t_out * 16 + brow) * 1024 + o) = r0;
        float l2 = acc[0][nj][2] + bx, l3 = acc[0][nj][3] + by;
        float q2 = acc[1][nj][2] + bx, q3 = acc[1][nj][3] + by;
        float2 r1 = make_float2(l2 * (1.0f / (1.0f + __expf(-q2))),
                                l3 * (1.0f / (1.0f + __expf(-q3))));
        *reinterpret_cast<float2*>(
            out + ((size_t)t_out * 16 + brow + 8) * 1024 + o) = r1;
    }
}

// ---------------------------------------------------------------------------
extern "C" void kernel_launch(void* const* d_in, const int* in_sizes, int n_in,
                              void* d_out, int out_size) {
    const float* src  = (const float*)d_in[0];   // src_tokens (32,8192,80) f32
    const void*  lens = d_in[1];                 // src_lengths (i32 or i64)
    const float* W    = (const float*)d_in[2];   // (1024, 640) f32
    const float* bias = (const float*)d_in[3];   // (1024,) f32
    float* out = (float*)d_out;

    cudaFuncSetAttribute(gemm_glu_kernel,
                         cudaFuncAttributeMaxDynamicSharedMemorySize, SMEM_BYTES);

    prep_kernel<<<XBLK + WBLK + 1, 256>>>(src, W, lens, out,
                                          (long long)out_size);

    dim3 grid(N_DIM / BN, (T_OUT * N_B) / BM);   // (8, 341)
    gemm_glu_kernel<<<grid, 512, SMEM_BYTES>>>(bias, out);
}

// round 17
// speedup vs baseline: 1.2609x; 1.2609x over previous
#include <cuda_runtime.h>
#include <cuda_fp16.h>
#include <stdint.h>
#include <stddef.h>

// ---------------------------------------------------------------------------
// SuperFrame: x[t,b,:] = src_flat[b*655360 + t*240 : +640]   (overlapping view)
// y = x @ W^T + b ; out[t,b,o] = y[t,b,o] * sigmoid(y[t,b+16,o]), b in [0,16)
// out_lengths = src_lengths//3 - 2
//
// fp16 mma.sync m16n8k16 (fp32 acc), eps 2^-11 => rel_err ~3.1e-4.
// R17 = R14 skeleton (BM=BN=128, 256 thr, 8 warps 4m x 2n, 3-stage cp.async,
// 2 CTAs/SM, wave-scheduled — the proven best) + two stall reducers:
//   (a) __expf (MUFU) in the GLU epilogue (was libm expf),
//   (b) cp.async prefetch spread across the 4 s-steps instead of a burst
//       at the stage boundary (smooths LSU/MIO contention with LDSM).
// ---------------------------------------------------------------------------

#define N_B   32
#define N_T   8192
#define N_F   80
#define T_OUT 2728              // (8192//3*3)/3 - 2
#define K_DIM 640
#define N_DIM 1024
#define BATCH_STRIDE 655360     // N_T*N_F elements

#define BM 128
#define BN 128
#define BK 64                   // 64 halfs = 128B per row
#define STAGES 3
#define KT 10                   // K_DIM/BK
#define A_STAGE_BYTES (BM*BK*2)           // 16384
#define B_STAGE_BYTES (BN*BK*2)           // 16384
#define SMEM_BYTES (STAGES*(A_STAGE_BYTES+B_STAGE_BYTES))  // 98304

#define NMAIN 44695552LL        // 2728*16*1024

// fp16 staging buffers (device globals: allocation-free scratch)
__device__ __half g_xh[(size_t)N_B*N_T*N_F];
__device__ __half g_wh[(size_t)N_DIM*K_DIM];

// ---------------------------------------------------------------------------
// Fused prep: blocks [0,20480) cvt x, [20480,21120) cvt w, block 21120 tail.
// ---------------------------------------------------------------------------
#define XBLK 20480              // 32*8192*80 / (256*4)
#define WBLK 640                // 1024*640  / (256*4)

__global__ void prep_kernel(const float* __restrict__ src,
                            const float* __restrict__ W,
                            const void* __restrict__ lens,
                            float* __restrict__ out, long long out_sz) {
    int b = blockIdx.x;
    if (b < XBLK) {
        int i = b * 256 + threadIdx.x;               // float4 index
        float4 v = reinterpret_cast<const float4*>(src)[i];
        __half2 lo = __floats2half2_rn(v.x, v.y);
        __half2 hi = __floats2half2_rn(v.z, v.w);
        uint2 o;
        o.x = *reinterpret_cast<unsigned int*>(&lo);
        o.y = *reinterpret_cast<unsigned int*>(&hi);
        reinterpret_cast<uint2*>(g_xh)[i] = o;
    } else if (b < XBLK + WBLK) {
        int i = (b - XBLK) * 256 + threadIdx.x;
        float4 v = reinterpret_cast<const float4*>(W)[i];
        __half2 lo = __floats2half2_rn(v.x, v.y);
        __half2 hi = __floats2half2_rn(v.z, v.w);
        uint2 o;
        o.x = *reinterpret_cast<unsigned int*>(&lo);
        o.y = *reinterpret_cast<unsigned int*>(&hi);
        reinterpret_cast<uint2*>(g_wh)[i] = o;
    } else {
        int i = threadIdx.x;
        if (i >= 32) return;
        long long rem = out_sz - NMAIN;
        const int* p32 = (const int*)lens;
        long long L = (p32[1] == 0) ? ((const long long*)lens)[i]
                                    : (long long)p32[i];
        long long v = L / 3 - 2;
        if (rem == 32) {
            out[NMAIN + i] = (float)v;               // lengths as f32 values
        } else if (rem == 64) {
            ((long long*)(out + NMAIN))[i] = v;      // raw int64 layout
        }
    }
}

// ---------------------------------------------------------------------------
// PTX helpers
// ---------------------------------------------------------------------------
__device__ __forceinline__ void cpasync16(uint32_t saddr, const void* gaddr) {
    asm volatile("cp.async.cg.shared.global [%0], [%1], 16;\n"
                 :: "r"(saddr), "l"(gaddr));
}
__device__ __forceinline__ void ldm4(uint32_t* r, uint32_t addr) {
    asm volatile("ldmatrix.sync.aligned.m8n8.x4.shared.b16 {%0,%1,%2,%3}, [%4];\n"
                 : "=r"(r[0]), "=r"(r[1]), "=r"(r[2]), "=r"(r[3]) : "r"(addr));
}
__device__ __forceinline__ void mma16816(float* c, const uint32_t* a,
                                         uint32_t b0, uint32_t b1) {
    asm volatile(
        "mma.sync.aligned.m16n8k16.row.col.f32.f16.f16.f32 "
        "{%0,%1,%2,%3}, {%4,%5,%6,%7}, {%8,%9}, {%0,%1,%2,%3};\n"
        : "+f"(c[0]), "+f"(c[1]), "+f"(c[2]), "+f"(c[3])
        : "r"(a[0]), "r"(a[1]), "r"(a[2]), "r"(a[3]), "r"(b0), "r"(b1));
}

// ---------------------------------------------------------------------------
// Fused GEMM + GLU kernel.
// grid = (8 ntiles, 682 mtiles), 256 threads, 8 warps in 4(m) x 2(n).
// m = t*32 + b ; warp_m owns one full t-group of 32 batches ->
// GLU pair (b, b+16) is (m-frag 0, m-frag 1) of the SAME thread.
// Pipeline: wait_group 1 -> barrier -> [per s-step: LDSM + 2 cp.async + MMA]
// -> commit. One barrier per k-tile; prefetch spread through the stage.
// ---------------------------------------------------------------------------
__global__ __launch_bounds__(256, 2)
void gemm_glu_kernel(const float* __restrict__ bias, float* __restrict__ out) {
    extern __shared__ char smem_raw[];
    const uint32_t sbase = (uint32_t)__cvta_generic_to_shared(smem_raw);
    const int tid  = threadIdx.x;
    const int lane = tid & 31;
    const int wid  = tid >> 5;
    const int warp_m = wid >> 1;          // 0..3
    const int warp_n = wid & 1;           // 0..1
    const int ntile = blockIdx.x;         // 0..7
    const int mtile = blockIdx.y;         // 0..681
    const int m0 = mtile * BM;
    const int n0 = ntile * BN;

    // ---- cp.async source/dest offsets (4 16B chunks/thread each) ----
    uint32_t ga[4], gb[4], sa[4];
    #pragma unroll
    for (int i = 0; i < 4; i++) {
        int c   = tid + i * 256;          // 0..1023
        int row = c >> 3;                 // 0..127
        int ch  = c & 7;                  // 16B chunk within 128B row
        int m   = m0 + row;
        ga[i] = (uint32_t)((m & 31) * BATCH_STRIDE + (m >> 5) * 240 + ch * 8);
        gb[i] = (uint32_t)((n0 + row) * K_DIM + ch * 8);
        sa[i] = (uint32_t)(row * 128 + ((ch ^ (row & 7)) << 4));  // xor swizzle
    }

    auto issue = [&](int st, int ko) {    // full-stage issue (prologue only)
        uint32_t aoff = sbase + st * A_STAGE_BYTES;
        uint32_t boff = sbase + STAGES * A_STAGE_BYTES + st * B_STAGE_BYTES;
        #pragma unroll
        for (int i = 0; i < 4; i++) {
            cpasync16(aoff + sa[i], g_xh + ga[i] + ko);
            cpasync16(boff + sa[i], g_wh + gb[i] + ko);
        }
    };

    float acc[2][8][4] = {};

    // prologue: fill first 2 stages
    issue(0, 0);
    asm volatile("cp.async.commit_group;\n");
    issue(1, BK);
    asm volatile("cp.async.commit_group;\n");

    #pragma unroll 1
    for (int kt = 0; kt < KT; kt++) {
        asm volatile("cp.async.wait_group 1;\n");   // stage kt landed
        __syncthreads();

        const int  pref = (kt + 2 < KT);
        const int  st2  = (kt + 2) % STAGES;
        const int  ko2  = (kt + 2) * BK;
        const uint32_t paoff = sbase + st2 * A_STAGE_BYTES;
        const uint32_t pboff = sbase + STAGES * A_STAGE_BYTES + st2 * B_STAGE_BYTES;

        uint32_t sA = sbase + (kt % STAGES) * A_STAGE_BYTES;
        uint32_t sB = sbase + STAGES * A_STAGE_BYTES + (kt % STAGES) * B_STAGE_BYTES;

        #pragma unroll
        for (int s = 0; s < 4; s++) {     // 4 k16-steps per BK=64
            uint32_t a[2][4];
            #pragma unroll
            for (int mi = 0; mi < 2; mi++) {
                int rl = warp_m * 32 + mi * 16 + (lane & 15);
                int ch = s * 2 + (lane >> 4);
                ldm4(a[mi], sA + rl * 128 + ((ch ^ (rl & 7)) << 4));
            }
            uint32_t bfr[4][4];
            #pragma unroll
            for (int g = 0; g < 4; g++) { // each x4 covers two n8 frags
                int nl = warp_n * 64 + g * 16 + ((lane >> 4) << 3) + (lane & 7);
                int ch = s * 2 + ((lane >> 3) & 1);
                ldm4(bfr[g], sB + nl * 128 + ((ch ^ (nl & 7)) << 4));
            }
            // spread prefetch: 1 A-chunk + 1 B-chunk of stage kt+2 per s-step
            if (pref) {
                cpasync16(paoff + sa[s], g_xh + ga[s] + ko2);
                cpasync16(pboff + sa[s], g_wh + gb[s] + ko2);
            }
            #pragma unroll
            for (int mi = 0; mi < 2; mi++)
                #pragma unroll
                for (int nj = 0; nj < 8; nj++)
                    mma16816(acc[mi][nj], a[mi],
                             bfr[nj >> 1][(nj & 1) * 2],
                             bfr[nj >> 1][(nj & 1) * 2 + 1]);
        }
        asm volatile("cp.async.commit_group;\n");   // unconditional: keeps count
    }

    // ---- fused GLU epilogue (thread-local (b, b+16) pairing), MUFU exp ----
    const int brow  = lane >> 2;          // 0..7
    const int col2  = (lane & 3) * 2;
    const int t_out = mtile * 4 + warp_m; // 0..2727
    #pragma unroll
    for (int nj = 0; nj < 8; nj++) {
        int o = n0 + warp_n * 64 + nj * 8 + col2;
        float bx = bias[o], by = bias[o + 1];
        float l0 = acc[0][nj][0] + bx, l1 = acc[0][nj][1] + by;
        float q0 = acc[1][nj][0] + bx, q1 = acc[1][nj][1] + by;
        float2 r0 = make_float2(l0 * (1.0f / (1.0f + __expf(-q0))),
                                l1 * (1.0f / (1.0f + __expf(-q1))));
        *reinterpret_cast<float2*>(
            out + ((size_t)t_out * 16 + brow) * 1024 + o) = r0;
        float l2 = acc[0][nj][2] + bx, l3 = acc[0][nj][3] + by;
        float q2 = acc[1][nj][2] + bx, q3 = acc[1][nj][3] + by;
        float2 r1 = make_float2(l2 * (1.0f / (1.0f + __expf(-q2))),
                                l3 * (1.0f / (1.0f + __expf(-q3))));
        *reinterpret_cast<float2*>(
            out + ((size_t)t_out * 16 + brow + 8) * 1024 + o) = r1;
    }
}

// ---------------------------------------------------------------------------
extern "C" void kernel_launch(void* const* d_in, const int* in_sizes, int n_in,
                              void* d_out, int out_size) {
    const float* src  = (const float*)d_in[0];   // src_tokens (32,8192,80) f32
    const void*  lens = d_in[1];                 // src_lengths (i32 or i64)
    const float* W    = (const float*)d_in[2];   // (1024, 640) f32
    const float* bias = (const float*)d_in[3];   // (1024,) f32
    float* out = (float*)d_out;

    cudaFuncSetAttribute(gemm_glu_kernel,
                         cudaFuncAttributeMaxDynamicSharedMemorySize, SMEM_BYTES);

    prep_kernel<<<XBLK + WBLK + 1, 256>>>(src, W, lens, out,
                                          (long long)out_size);

    dim3 grid(N_DIM / BN, (T_OUT * N_B) / BM);   // (8, 682)
    gemm_glu_kernel<<<grid, 256, SMEM_BYTES>>>(bias, out);
}